// round 11
// baseline (speedup 1.0000x reference)
#include <cuda_runtime.h>
#include <cuda_bf16.h>
#include <cstdint>

// DIN sequence encoder, B=4096, L=200, E=A=128.
// Factorization: att_in@W1 = q@(W1a+W1c) + keys_p@[(W1b-W1c) + diag(q)*W1d]
// 256 threads/CTA, 2 CTAs/SM. mma.sync bf16 3-term split, 32x32 warp tiles.
// B1 (q-dependent) pre-built as mma fragment images in gmem (bstage kernel);
// A-tile staging for tile t+1 hidden inside tile t's GEMM1 k-loop.

#define EB 128
#define AB 128
#define LK 200
#define NB 4096
#define LDAE 136
#define LDAB (LDAE * 2)          // 272 B row stride

__device__ float g_W1kT[EB * AB];                    // [n][e] = (W1b - W1c)^T
__device__ float g_W1dT[EB * AB];                    // [n][e] = W1d^T
__device__ __align__(16) uint32_t g_W2fh[8192];      // W2 fragment images (hi)
__device__ __align__(16) uint32_t g_W2fl[8192];      // W2 fragment images (lo)
__device__ __align__(16) uint32_t g_B1fh[(size_t)NB * 8192];  // per-batch B1 frags hi
__device__ __align__(16) uint32_t g_B1fl[(size_t)NB * 8192];  // per-batch B1 frags lo
__device__ float g_U[NB * AB];                       // u = q @ (W1a+W1c) + b1
__device__ int   g_len64;

// fast fp32 -> bf16 hi/lo split, packed pairs (x0 in low half)
__device__ __forceinline__ uint32_t packsplit(float x0, float x1, uint32_t& lop) {
    uint32_t hip;
    asm("cvt.rn.bf16x2.f32 %0, %1, %2;" : "=r"(hip) : "f"(x1), "f"(x0));
    float h0 = __uint_as_float(hip << 16);
    float h1 = __uint_as_float(hip & 0xFFFF0000u);
    float r0 = x0 - h0, r1 = x1 - h1;
    asm("cvt.rn.bf16x2.f32 %0, %1, %2;" : "=r"(lop) : "f"(r1), "f"(r0));
    return hip;
}

// ---------------- prep kernel: grid 161 x 256 ----------------
__global__ void prep_kernel(const float* __restrict__ W1,
                            const float* __restrict__ b1,
                            const float* __restrict__ W2,
                            const float* __restrict__ query,
                            const unsigned int* __restrict__ kl_words, int B) {
    extern __shared__ float sp[];
    const int t = threadIdx.x;
    const int blk = blockIdx.x;

    if (blk < 64) {                       // W1 transposes (fp32)
        int i = blk * 256 + t;
        int e = i >> 7, n = i & 127;
        g_W1kT[n * EB + e] = W1[EB * AB + e * AB + n] - W1[2 * EB * AB + e * AB + n];
        g_W1dT[n * EB + e] = W1[3 * EB * AB + e * AB + n];
        return;
    }
    if (blk < 96) {                       // W2 fragment images for mma B operand
        int i = (blk - 64) * 256 + t;     // 0..8191
        int j = i & 3, lane = (i >> 2) & 31, ng = (i >> 7) & 7, s = i >> 10;
        int n  = ng * 16 + ((j >> 1) << 3) + (lane >> 2);
        int k0 = s * 16 + (lane & 3) * 2 + ((j & 1) ? 8 : 0);
        float a = W2[k0 * AB + n];
        float bv = W2[(k0 + 1) * AB + n];
        uint32_t lop, hip = packsplit(a, bv, lop);
        g_W2fh[i] = hip;
        g_W2fl[i] = lop;
        return;
    }
    if (blk == 96) {                      // keys_length dtype sniffer
        int local = 0;
        for (int i = t; i < B / 2; i += 256)
            if (kl_words[2 * i + 1] != 0u) local = 1;
        int any = __syncthreads_or(local);
        if (t == 0) g_len64 = any ? 0 : 1;
        return;
    }

    // g_U blocks (97..160)
    float* sW = sp;            // 16384: W1a + W1c
    float* sq = sp + 16384;    // 128
    for (int i = t; i < EB * AB; i += 256)
        sW[i] = W1[i] + W1[2 * EB * AB + i];
    __syncthreads();
    int bid2 = blk - 97;
    for (int bb2 = 0; bb2 < 64; bb2++) {
        int bb = bid2 * 64 + bb2;
        if (t < 128) sq[t] = query[(size_t)bb * EB + t];
        __syncthreads();
        if (t < 128) {
            float acc = b1[t];
            #pragma unroll 8
            for (int e = 0; e < EB; e++) acc += sq[e] * sW[e * AB + t];
            g_U[(size_t)bb * AB + t] = acc;
        }
        __syncthreads();
    }
}

// ---------------- bstage kernel: per-batch B1 fragment images ----------------
__global__ void bstage_kernel(const float* __restrict__ query) {
    __shared__ float sq[128];
    const int b = blockIdx.x, t = threadIdx.x;
    if (t < 128) sq[t] = query[(size_t)b * EB + t];
    __syncthreads();
    uint32_t* outh = g_B1fh + (size_t)b * 8192;
    uint32_t* outl = g_B1fl + (size_t)b * 8192;
    #pragma unroll 4
    for (int ii = 0; ii < 32; ii++) {
        int i = ii * 256 + t;
        int j = i & 3, lane = (i >> 2) & 31, ng = (i >> 7) & 7, s = i >> 10;
        int n  = ng * 16 + ((j >> 1) << 3) + (lane >> 2);
        int k0 = s * 16 + (lane & 3) * 2 + ((j & 1) ? 8 : 0);
        float x0 = g_W1kT[n * EB + k0]     + sq[k0]     * g_W1dT[n * EB + k0];
        float x1 = g_W1kT[n * EB + k0 + 1] + sq[k0 + 1] * g_W1dT[n * EB + k0 + 1];
        uint32_t lop, hip = packsplit(x0, x1, lop);
        outh[i] = hip;
        outl[i] = lop;
    }
}

// ---------------- MMA helpers ----------------
__device__ __forceinline__ uint32_t smem_u32(const void* p) {
    uint32_t a;
    asm("{ .reg .u64 tmp; cvta.to.shared.u64 tmp, %1; cvt.u32.u64 %0, tmp; }"
        : "=r"(a) : "l"(p));
    return a;
}
__device__ __forceinline__ void ldsm_x4(uint32_t* r, uint32_t addr) {
    asm volatile("ldmatrix.sync.aligned.m8n8.x4.shared.b16 {%0,%1,%2,%3}, [%4];"
                 : "=r"(r[0]), "=r"(r[1]), "=r"(r[2]), "=r"(r[3]) : "r"(addr));
}
__device__ __forceinline__ void mma_bf16(float* d, const uint32_t* a,
                                         uint32_t b0, uint32_t b1) {
    asm volatile("mma.sync.aligned.m16n8k16.row.col.f32.bf16.bf16.f32 "
                 "{%0,%1,%2,%3},{%4,%5,%6,%7},{%8,%9},{%0,%1,%2,%3};"
                 : "+f"(d[0]), "+f"(d[1]), "+f"(d[2]), "+f"(d[3])
                 : "r"(a[0]), "r"(a[1]), "r"(a[2]), "r"(a[3]), "r"(b0), "r"(b1));
}

// ---------------- SMEM layout (bytes) ----------------
#define OFF_A0HI 0                        // 64*272 = 17408
#define OFF_A0LO 17408
#define OFF_A1HI 34816
#define OFF_A1LO 52224
#define OFF_U    69632                    // 128 f
#define OFF_BB2  70144
#define OFF_W3   70656
#define OFF_SC   71168                    // 256 f
#define OFF_RED  72192                    // 512 f
#define SMEM_BYTES 74240

__global__ void __launch_bounds__(256, 2) din_kernel(
    const float* __restrict__ keys,
    const void*  __restrict__ keys_length,
    const float* __restrict__ pos_emb,
    const float* __restrict__ b2,
    const float* __restrict__ W3,
    const float* __restrict__ b3,
    float* __restrict__ out)
{
    extern __shared__ char smc[];
    float* sU   = (float*)(smc + OFF_U);
    float* sBB  = (float*)(smc + OFF_BB2);
    float* sW3  = (float*)(smc + OFF_W3);
    float* sSc  = (float*)(smc + OFF_SC);
    float* sRed = (float*)(smc + OFF_RED);

    const int b = blockIdx.x;
    const int t = threadIdx.x;
    const int w = t >> 5, lane = t & 31;

    if (t < 128) {
        sU[t]  = g_U[(size_t)b * AB + t];
        sBB[t] = b2[t];
        sW3[t] = W3[t];
    }
    const float b3v = b3[0];
    const float* kb = keys + (size_t)b * LK * EB;

    // ---- stage tile 0 into buffer 0 ----
    {
        uint32_t* hi = (uint32_t*)(smc + OFF_A0HI);
        uint32_t* lo = (uint32_t*)(smc + OFF_A0LO);
        #pragma unroll
        for (int si = 0; si < 8; si++) {
            int idx = si * 256 + t;
            int l = idx >> 5, e4 = (idx & 31) * 4;
            float x0 = 0, x1 = 0, x2 = 0, x3 = 0;
            {
                float4 kv = *(const float4*)(kb + (size_t)l * EB + e4);
                float4 pv = *(const float4*)(pos_emb + (size_t)l * EB + e4);
                x0 = kv.x + pv.x; x1 = kv.y + pv.y; x2 = kv.z + pv.z; x3 = kv.w + pv.w;
            }
            uint32_t lo0, hi0 = packsplit(x0, x1, lo0);
            uint32_t lo1, hi1 = packsplit(x2, x3, lo1);
            *(uint2*)(hi + l * 68 + (e4 >> 1)) = make_uint2(hi0, hi1);
            *(uint2*)(lo + l * 68 + (e4 >> 1)) = make_uint2(lo0, lo1);
        }
    }
    __syncthreads();

    // 32x32 warp tiles: 2 m-groups x 4 n-groups
    const int wm = w >> 2, wn = w & 3;
    const int m0 = wm * 32, n0 = wn * 32;
    const uint32_t lrow  = (((lane >> 3) & 1) << 3) + (lane & 7);
    const uint32_t lcolb = (lane >> 4) << 4;
    const uint32_t aOff  = (m0 + lrow) * LDAB + lcolb;

    const uint32_t a0Hi = smem_u32(smc + OFF_A0HI) + aOff;
    const uint32_t a0Lo = smem_u32(smc + OFF_A0LO) + aOff;
    const uint32_t a1Hi = smem_u32(smc + OFF_A1HI) + aOff;
    const uint32_t a1Lo = smem_u32(smc + OFF_A1LO) + aOff;

    const uint4* W2fh4 = (const uint4*)g_W2fh;
    const uint4* W2fl4 = (const uint4*)g_W2fl;
    const uint4* B1fh4 = (const uint4*)(g_B1fh + (size_t)b * 8192);
    const uint4* B1fl4 = (const uint4*)(g_B1fl + (size_t)b * 8192);
    const int ng0 = wn * 2, ng1 = wn * 2 + 1;

    for (int tile = 0; tile < 4; tile++) {
        const int cur = tile & 1;
        const uint32_t aHi = cur ? a1Hi : a0Hi;
        const uint32_t aLo = cur ? a1Lo : a0Lo;
        uint32_t* nHi = (uint32_t*)(smc + (cur ? OFF_A0HI : OFF_A1HI));
        uint32_t* nLo = (uint32_t*)(smc + (cur ? OFF_A0LO : OFF_A1LO));
        const bool doStage = (tile < 3);
        const int nl0 = (tile + 1) * 64;

        float acc[2][4][4];
        #pragma unroll
        for (int mt = 0; mt < 2; mt++)
            #pragma unroll
            for (int nt = 0; nt < 4; nt++)
                #pragma unroll
                for (int r = 0; r < 4; r++) acc[mt][nt][r] = 0.0f;

        // ---- layer 1 GEMM (pipelined), staging of tile+1 interleaved ----
        {
            uint32_t ah[2][2][4], al[2][2][4];
            uint4 bh[2][2], bl[2][2];
            #define LOADG1(buf, kk) do { \
                ldsm_x4(ah[buf][0], aHi + (kk) * 32); \
                ldsm_x4(ah[buf][1], aHi + 16 * LDAB + (kk) * 32); \
                ldsm_x4(al[buf][0], aLo + (kk) * 32); \
                ldsm_x4(al[buf][1], aLo + 16 * LDAB + (kk) * 32); \
                bh[buf][0] = B1fh4[((kk) * 8 + ng0) * 32 + lane]; \
                bh[buf][1] = B1fh4[((kk) * 8 + ng1) * 32 + lane]; \
                bl[buf][0] = B1fl4[((kk) * 8 + ng0) * 32 + lane]; \
                bl[buf][1] = B1fl4[((kk) * 8 + ng1) * 32 + lane]; \
            } while (0)

            float4 skv, spv;            // staging pipeline regs
            bool sval = false;
            #define STAGE_LD(si) do { \
                int idx = (si) * 256 + t; \
                int l = idx >> 5, e4 = (idx & 31) * 4; \
                int gl = nl0 + l; \
                sval = (gl < LK); \
                if (sval) { \
                    skv = *(const float4*)(kb + (size_t)gl * EB + e4); \
                    spv = *(const float4*)(pos_emb + (size_t)gl * EB + e4); \
                } \
            } while (0)
            #define STAGE_ST(si) do { \
                int idx = (si) * 256 + t; \
                int l = idx >> 5, e4 = (idx & 31) * 4; \
                float x0 = 0, x1 = 0, x2 = 0, x3 = 0; \
                if (sval) { \
                    x0 = skv.x + spv.x; x1 = skv.y + spv.y; \
                    x2 = skv.z + spv.z; x3 = skv.w + spv.w; \
                } \
                uint32_t lo0, hi0 = packsplit(x0, x1, lo0); \
                uint32_t lo1, hi1 = packsplit(x2, x3, lo1); \
                *(uint2*)(nHi + l * 68 + (e4 >> 1)) = make_uint2(hi0, hi1); \
                *(uint2*)(nLo + l * 68 + (e4 >> 1)) = make_uint2(lo0, lo1); \
            } while (0)

            LOADG1(0, 0);
            if (doStage) STAGE_LD(0);
            #pragma unroll
            for (int k = 0; k < 8; k++) {
                const int cb = k & 1, nb = cb ^ 1;
                if (k < 7) LOADG1(nb, k + 1);
                if (doStage && k > 0) { STAGE_ST(k - 1); STAGE_LD(k); }
                #pragma unroll
                for (int mt = 0; mt < 2; mt++) {
                    mma_bf16(acc[mt][0], ah[cb][mt], bh[cb][0].x, bh[cb][0].y);
                    mma_bf16(acc[mt][1], ah[cb][mt], bh[cb][0].z, bh[cb][0].w);
                    mma_bf16(acc[mt][2], ah[cb][mt], bh[cb][1].x, bh[cb][1].y);
                    mma_bf16(acc[mt][3], ah[cb][mt], bh[cb][1].z, bh[cb][1].w);
                }
                #pragma unroll
                for (int mt = 0; mt < 2; mt++) {
                    mma_bf16(acc[mt][0], ah[cb][mt], bl[cb][0].x, bl[cb][0].y);
                    mma_bf16(acc[mt][1], ah[cb][mt], bl[cb][0].z, bl[cb][0].w);
                    mma_bf16(acc[mt][2], ah[cb][mt], bl[cb][1].x, bl[cb][1].y);
                    mma_bf16(acc[mt][3], ah[cb][mt], bl[cb][1].z, bl[cb][1].w);
                }
                #pragma unroll
                for (int mt = 0; mt < 2; mt++) {
                    mma_bf16(acc[mt][0], al[cb][mt], bh[cb][0].x, bh[cb][0].y);
                    mma_bf16(acc[mt][1], al[cb][mt], bh[cb][0].z, bh[cb][0].w);
                    mma_bf16(acc[mt][2], al[cb][mt], bh[cb][1].x, bh[cb][1].y);
                    mma_bf16(acc[mt][3], al[cb][mt], bh[cb][1].z, bh[cb][1].w);
                }
            }
            if (doStage) STAGE_ST(7);
            #undef LOADG1
            #undef STAGE_LD
            #undef STAGE_ST
        }
        __syncthreads();   // A reads + staging done

        // ---- epilogue 1: H1 = relu(z1 + u) -> current A buffer ----
        {
            uint32_t* hi = (uint32_t*)(smc + (cur ? OFF_A1HI : OFF_A0HI));
            uint32_t* lo = (uint32_t*)(smc + (cur ? OFF_A1LO : OFF_A0LO));
            const int rrow = lane >> 2;
            const int ccol = (lane & 3) * 2;
            #pragma unroll
            for (int mt = 0; mt < 2; mt++) {
                #pragma unroll
                for (int nt = 0; nt < 4; nt++) {
                    int c = n0 + nt * 8 + ccol;
                    float u0 = sU[c], u1 = sU[c + 1];
                    int r0 = m0 + mt * 16 + rrow;
                    float h0 = fmaxf(acc[mt][nt][0] + u0, 0.0f);
                    float h1 = fmaxf(acc[mt][nt][1] + u1, 0.0f);
                    uint32_t lop, hip = packsplit(h0, h1, lop);
                    uint32_t wi = r0 * 68 + (c >> 1);
                    hi[wi] = hip; lo[wi] = lop;
                    h0 = fmaxf(acc[mt][nt][2] + u0, 0.0f);
                    h1 = fmaxf(acc[mt][nt][3] + u1, 0.0f);
                    hip = packsplit(h0, h1, lop);
                    wi = (r0 + 8) * 68 + (c >> 1);
                    hi[wi] = hip; lo[wi] = lop;
                }
            }
        }
        __syncthreads();

        // ---- layer 2 GEMM (pipelined W2 from gmem) ----
        #pragma unroll
        for (int mt = 0; mt < 2; mt++)
            #pragma unroll
            for (int nt = 0; nt < 4; nt++)
                #pragma unroll
                for (int r = 0; r < 4; r++) acc[mt][nt][r] = 0.0f;

        {
            uint32_t ah[2][2][4], al[2][2][4];
            uint4 bh[2][2], bl[2][2];
            #define LOADG2(buf, kk) do { \
                ldsm_x4(ah[buf][0], aHi + (kk) * 32); \
                ldsm_x4(ah[buf][1], aHi + 16 * LDAB + (kk) * 32); \
                ldsm_x4(al[buf][0], aLo + (kk) * 32); \
                ldsm_x4(al[buf][1], aLo + 16 * LDAB + (kk) * 32); \
                bh[buf][0] = W2fh4[((kk) * 8 + ng0) * 32 + lane]; \
                bh[buf][1] = W2fh4[((kk) * 8 + ng1) * 32 + lane]; \
                bl[buf][0] = W2fl4[((kk) * 8 + ng0) * 32 + lane]; \
                bl[buf][1] = W2fl4[((kk) * 8 + ng1) * 32 + lane]; \
            } while (0)
            LOADG2(0, 0);
            #pragma unroll
            for (int k = 0; k < 8; k++) {
                const int cb = k & 1, nb = cb ^ 1;
                if (k < 7) LOADG2(nb, k + 1);
                #pragma unroll
                for (int mt = 0; mt < 2; mt++) {
                    mma_bf16(acc[mt][0], ah[cb][mt], bh[cb][0].x, bh[cb][0].y);
                    mma_bf16(acc[mt][1], ah[cb][mt], bh[cb][0].z, bh[cb][0].w);
                    mma_bf16(acc[mt][2], ah[cb][mt], bh[cb][1].x, bh[cb][1].y);
                    mma_bf16(acc[mt][3], ah[cb][mt], bh[cb][1].z, bh[cb][1].w);
                }
                #pragma unroll
                for (int mt = 0; mt < 2; mt++) {
                    mma_bf16(acc[mt][0], ah[cb][mt], bl[cb][0].x, bl[cb][0].y);
                    mma_bf16(acc[mt][1], ah[cb][mt], bl[cb][0].z, bl[cb][0].w);
                    mma_bf16(acc[mt][2], ah[cb][mt], bl[cb][1].x, bl[cb][1].y);
                    mma_bf16(acc[mt][3], ah[cb][mt], bl[cb][1].z, bl[cb][1].w);
                }
                #pragma unroll
                for (int mt = 0; mt < 2; mt++) {
                    mma_bf16(acc[mt][0], al[cb][mt], bh[cb][0].x, bh[cb][0].y);
                    mma_bf16(acc[mt][1], al[cb][mt], bh[cb][0].z, bh[cb][0].w);
                    mma_bf16(acc[mt][2], al[cb][mt], bh[cb][1].x, bh[cb][1].y);
                    mma_bf16(acc[mt][3], al[cb][mt], bh[cb][1].z, bh[cb][1].w);
                }
            }
            #undef LOADG2
        }

        // ---- epilogue 2: per-row partial scores ----
        {
            const int ccol = (lane & 3) * 2;
            #pragma unroll
            for (int mt = 0; mt < 2; mt++) {
                float p0 = 0.0f, p1 = 0.0f;
                #pragma unroll
                for (int nt = 0; nt < 4; nt++) {
                    int c = n0 + nt * 8 + ccol;
                    float bb0 = sBB[c], bb1 = sBB[c + 1];
                    float w30 = sW3[c], w31 = sW3[c + 1];
                    p0 += fmaxf(acc[mt][nt][0] + bb0, 0.0f) * w30
                        + fmaxf(acc[mt][nt][1] + bb1, 0.0f) * w31;
                    p1 += fmaxf(acc[mt][nt][2] + bb0, 0.0f) * w30
                        + fmaxf(acc[mt][nt][3] + bb1, 0.0f) * w31;
                }
                p0 += __shfl_xor_sync(0xffffffffu, p0, 1);
                p0 += __shfl_xor_sync(0xffffffffu, p0, 2);
                p1 += __shfl_xor_sync(0xffffffffu, p1, 1);
                p1 += __shfl_xor_sync(0xffffffffu, p1, 2);
                if ((lane & 3) == 0) {
                    int r = m0 + mt * 16 + (lane >> 2);
                    sRed[r * 4 + wn]       = p0;
                    sRed[(r + 8) * 4 + wn] = p1;
                }
            }
        }
        __syncthreads();

        if (t < 64) {
            float s4 = sRed[t * 4] + sRed[t * 4 + 1] + sRed[t * 4 + 2] + sRed[t * 4 + 3];
            sSc[tile * 64 + t] = s4 + b3v;
        }
    }
    __syncthreads();

    // ---- softmax over valid l ----
    int kli;
    if (g_len64) kli = (int)((const long long*)keys_length)[b];
    else         kli = ((const int*)keys_length)[b];
    kli = min(max(kli, 0), LK);

    float s = (t < kli) ? sSc[t] : -3.0e38f;
    float mw = s;
    #pragma unroll
    for (int off = 16; off > 0; off >>= 1)
        mw = fmaxf(mw, __shfl_down_sync(0xffffffffu, mw, off));
    if (lane == 0) sRed[w] = mw;
    __syncthreads();
    float m = sRed[0];
    #pragma unroll
    for (int ww = 1; ww < 8; ww++) m = fmaxf(m, sRed[ww]);

    float wgt = (t < kli) ? expf(s - m) : 0.0f;
    sSc[t] = wgt;
    float sw = wgt;
    #pragma unroll
    for (int off = 16; off > 0; off >>= 1)
        sw += __shfl_down_sync(0xffffffffu, sw, off);
    if (lane == 0) sRed[8 + w] = sw;
    __syncthreads();
    float tot = 0.0f;
    #pragma unroll
    for (int ww = 0; ww < 8; ww++) tot += sRed[8 + ww];
    const float inv = 1.0f / tot;
    __syncthreads();

    // ---- weighted sum of keys_p ----
    {
        int ei = t & 127, half = t >> 7;
        float acc2 = 0.0f;
        #pragma unroll 4
        for (int l = half; l < kli; l += 2)
            acc2 += sSc[l] * (kb[(size_t)l * EB + ei] + pos_emb[(size_t)l * EB + ei]);
        sRed[t] = acc2;
        __syncthreads();
        if (t < 128)
            out[(size_t)b * EB + t] = (sRed[t] + sRed[t + 128]) * inv;
    }
}

extern "C" void kernel_launch(void* const* d_in, const int* in_sizes, int n_in,
                              void* d_out, int out_size) {
    const float* query       = (const float*)d_in[0];
    const float* keys        = (const float*)d_in[1];
    const void*  keys_length = d_in[2];
    const float* pos_emb     = (const float*)d_in[3];
    const float* W1          = (const float*)d_in[4];
    const float* b1          = (const float*)d_in[5];
    const float* W2          = (const float*)d_in[6];
    const float* b2          = (const float*)d_in[7];
    const float* W3          = (const float*)d_in[8];
    const float* b3          = (const float*)d_in[9];
    float* out = (float*)d_out;

    const int B = in_sizes[2];  // 4096

    static int attr_done = 0;
    if (!attr_done) {
        cudaFuncSetAttribute(prep_kernel, cudaFuncAttributeMaxDynamicSharedMemorySize, 16512 * 4);
        cudaFuncSetAttribute(din_kernel,  cudaFuncAttributeMaxDynamicSharedMemorySize, SMEM_BYTES);
        attr_done = 1;
    }

    prep_kernel<<<161, 256, 16512 * 4>>>(W1, b1, W2, query,
                                         (const unsigned int*)keys_length, B);
    bstage_kernel<<<NB, 256>>>(query);
    din_kernel<<<NB, 256, SMEM_BYTES>>>(keys, keys_length, pos_emb,
                                        b2, W3, b3, out);
}

// round 14
// speedup vs baseline: 1.1022x; 1.1022x over previous
#include <cuda_runtime.h>
#include <cuda_bf16.h>
#include <cstdint>

// DIN sequence encoder, B=4096, L=200, E=A=128.
// Factorization: att_in@W1 = q@(W1a+W1c) + keys_p@[(W1b-W1c) + diag(q)*W1d]
// 256 threads/CTA, 2 CTAs/SM. mma.sync bf16 3-term split, 32x32 warp tiles.
// B1 (q-dependent) pre-built as mma fragment images in gmem (bstage kernel,
// which also computes the per-batch bias u). A-tile staging for tile t+1 is
// hidden inside tile t's GEMM1 k-loop.

#define EB 128
#define AB 128
#define LK 200
#define NB 4096
#define LDAE 136
#define LDAB (LDAE * 2)          // 272 B row stride

__device__ float g_W1kT[EB * AB];                    // [n][e] = (W1b - W1c)^T
__device__ float g_W1dT[EB * AB];                    // [n][e] = W1d^T
__device__ float g_W1q[EB * AB];                     // [e][n] = W1a + W1c
__device__ __align__(16) uint32_t g_W2fh[8192];      // W2 fragment images (hi)
__device__ __align__(16) uint32_t g_W2fl[8192];      // W2 fragment images (lo)
__device__ __align__(16) uint32_t g_B1fh[(size_t)NB * 8192];  // per-batch B1 frags hi
__device__ __align__(16) uint32_t g_B1fl[(size_t)NB * 8192];  // per-batch B1 frags lo
__device__ float g_U[NB * AB];                       // u = q @ (W1a+W1c) + b1
__device__ int   g_len64;

// fast fp32 -> bf16 hi/lo split, packed pairs (x0 in low half)
__device__ __forceinline__ uint32_t packsplit(float x0, float x1, uint32_t& lop) {
    uint32_t hip;
    asm("cvt.rn.bf16x2.f32 %0, %1, %2;" : "=r"(hip) : "f"(x1), "f"(x0));
    float h0 = __uint_as_float(hip << 16);
    float h1 = __uint_as_float(hip & 0xFFFF0000u);
    float r0 = x0 - h0, r1 = x1 - h1;
    asm("cvt.rn.bf16x2.f32 %0, %1, %2;" : "=r"(lop) : "f"(r1), "f"(r0));
    return hip;
}

// ---------------- prep kernel: grid 97 x 256 (all-parallel, ~6us) ----------------
__global__ void prep_kernel(const float* __restrict__ W1,
                            const float* __restrict__ W2,
                            const unsigned int* __restrict__ kl_words, int B) {
    const int t = threadIdx.x;
    const int blk = blockIdx.x;

    if (blk < 64) {                       // W1 transposes + W1q sum (fp32)
        int i = blk * 256 + t;
        int e = i >> 7, n = i & 127;
        float wa = W1[e * AB + n];
        float wb = W1[EB * AB + e * AB + n];
        float wc = W1[2 * EB * AB + e * AB + n];
        float wd = W1[3 * EB * AB + e * AB + n];
        g_W1kT[n * EB + e] = wb - wc;
        g_W1dT[n * EB + e] = wd;
        g_W1q[i] = wa + wc;               // [e][n]
        return;
    }
    if (blk < 96) {                       // W2 fragment images for mma B operand
        int i = (blk - 64) * 256 + t;     // 0..8191
        int j = i & 3, lane = (i >> 2) & 31, ng = (i >> 7) & 7, s = i >> 10;
        int n  = ng * 16 + ((j >> 1) << 3) + (lane >> 2);
        int k0 = s * 16 + (lane & 3) * 2 + ((j & 1) ? 8 : 0);
        float a = W2[k0 * AB + n];
        float bv = W2[(k0 + 1) * AB + n];
        uint32_t lop, hip = packsplit(a, bv, lop);
        g_W2fh[i] = hip;
        g_W2fl[i] = lop;
        return;
    }
    // blk == 96: keys_length dtype sniffer
    int local = 0;
    for (int i = t; i < B / 2; i += 256)
        if (kl_words[2 * i + 1] != 0u) local = 1;
    int any = __syncthreads_or(local);
    if (t == 0) g_len64 = any ? 0 : 1;
}

// ---------------- bstage kernel: per-batch B1 fragment images + u ----------------
__global__ void bstage_kernel(const float* __restrict__ query,
                              const float* __restrict__ b1) {
    __shared__ float sq[128];
    __shared__ float su[2][128];
    const int b = blockIdx.x, t = threadIdx.x;
    if (t < 128) sq[t] = query[(size_t)b * EB + t];
    __syncthreads();

    // ---- u = q @ (W1a+W1c) + b1, split across 2 thread halves ----
    {
        int n = t & 127, half = t >> 7;
        float acc = 0.0f;
        #pragma unroll 8
        for (int e = half * 64; e < half * 64 + 64; e++)
            acc += sq[e] * g_W1q[e * AB + n];
        su[half][n] = acc;
    }

    // ---- B1 fragment images ----
    uint32_t* outh = g_B1fh + (size_t)b * 8192;
    uint32_t* outl = g_B1fl + (size_t)b * 8192;
    #pragma unroll 4
    for (int ii = 0; ii < 32; ii++) {
        int i = ii * 256 + t;
        int j = i & 3, lane = (i >> 2) & 31, ng = (i >> 7) & 7, s = i >> 10;
        int n  = ng * 16 + ((j >> 1) << 3) + (lane >> 2);
        int k0 = s * 16 + (lane & 3) * 2 + ((j & 1) ? 8 : 0);
        float x0 = g_W1kT[n * EB + k0]     + sq[k0]     * g_W1dT[n * EB + k0];
        float x1 = g_W1kT[n * EB + k0 + 1] + sq[k0 + 1] * g_W1dT[n * EB + k0 + 1];
        uint32_t lop, hip = packsplit(x0, x1, lop);
        outh[i] = hip;
        outl[i] = lop;
    }

    __syncthreads();
    if (t < 128) g_U[(size_t)b * AB + t] = su[0][t] + su[1][t] + b1[t];
}

// ---------------- MMA helpers ----------------
__device__ __forceinline__ uint32_t smem_u32(const void* p) {
    uint32_t a;
    asm("{ .reg .u64 tmp; cvta.to.shared.u64 tmp, %1; cvt.u32.u64 %0, tmp; }"
        : "=r"(a) : "l"(p));
    return a;
}
__device__ __forceinline__ void ldsm_x4(uint32_t* r, uint32_t addr) {
    asm volatile("ldmatrix.sync.aligned.m8n8.x4.shared.b16 {%0,%1,%2,%3}, [%4];"
                 : "=r"(r[0]), "=r"(r[1]), "=r"(r[2]), "=r"(r[3]) : "r"(addr));
}
__device__ __forceinline__ void mma_bf16(float* d, const uint32_t* a,
                                         uint32_t b0, uint32_t b1) {
    asm volatile("mma.sync.aligned.m16n8k16.row.col.f32.bf16.bf16.f32 "
                 "{%0,%1,%2,%3},{%4,%5,%6,%7},{%8,%9},{%0,%1,%2,%3};"
                 : "+f"(d[0]), "+f"(d[1]), "+f"(d[2]), "+f"(d[3])
                 : "r"(a[0]), "r"(a[1]), "r"(a[2]), "r"(a[3]), "r"(b0), "r"(b1));
}

// ---------------- SMEM layout (bytes) ----------------
#define OFF_A0HI 0                        // 64*272 = 17408
#define OFF_A0LO 17408
#define OFF_A1HI 34816
#define OFF_A1LO 52224
#define OFF_U    69632                    // 128 f
#define OFF_BB2  70144
#define OFF_W3   70656
#define OFF_SC   71168                    // 256 f
#define OFF_RED  72192                    // 512 f
#define SMEM_BYTES 74240

__global__ void __launch_bounds__(256, 2) din_kernel(
    const float* __restrict__ keys,
    const void*  __restrict__ keys_length,
    const float* __restrict__ pos_emb,
    const float* __restrict__ b2,
    const float* __restrict__ W3,
    const float* __restrict__ b3,
    float* __restrict__ out)
{
    extern __shared__ char smc[];
    float* sU   = (float*)(smc + OFF_U);
    float* sBB  = (float*)(smc + OFF_BB2);
    float* sW3  = (float*)(smc + OFF_W3);
    float* sSc  = (float*)(smc + OFF_SC);
    float* sRed = (float*)(smc + OFF_RED);

    const int b = blockIdx.x;
    const int t = threadIdx.x;
    const int w = t >> 5, lane = t & 31;

    if (t < 128) {
        sU[t]  = g_U[(size_t)b * AB + t];
        sBB[t] = b2[t];
        sW3[t] = W3[t];
    }
    const float b3v = b3[0];
    const float* kb = keys + (size_t)b * LK * EB;

    // ---- stage tile 0 into buffer 0 ----
    {
        uint32_t* hi = (uint32_t*)(smc + OFF_A0HI);
        uint32_t* lo = (uint32_t*)(smc + OFF_A0LO);
        #pragma unroll
        for (int si = 0; si < 8; si++) {
            int idx = si * 256 + t;
            int l = idx >> 5, e4 = (idx & 31) * 4;
            float x0 = 0, x1 = 0, x2 = 0, x3 = 0;
            {
                float4 kv = *(const float4*)(kb + (size_t)l * EB + e4);
                float4 pv = *(const float4*)(pos_emb + (size_t)l * EB + e4);
                x0 = kv.x + pv.x; x1 = kv.y + pv.y; x2 = kv.z + pv.z; x3 = kv.w + pv.w;
            }
            uint32_t lo0, hi0 = packsplit(x0, x1, lo0);
            uint32_t lo1, hi1 = packsplit(x2, x3, lo1);
            *(uint2*)(hi + l * 68 + (e4 >> 1)) = make_uint2(hi0, hi1);
            *(uint2*)(lo + l * 68 + (e4 >> 1)) = make_uint2(lo0, lo1);
        }
    }
    __syncthreads();

    // 32x32 warp tiles: 2 m-groups x 4 n-groups
    const int wm = w >> 2, wn = w & 3;
    const int m0 = wm * 32, n0 = wn * 32;
    const uint32_t lrow  = (((lane >> 3) & 1) << 3) + (lane & 7);
    const uint32_t lcolb = (lane >> 4) << 4;
    const uint32_t aOff  = (m0 + lrow) * LDAB + lcolb;

    const uint32_t a0Hi = smem_u32(smc + OFF_A0HI) + aOff;
    const uint32_t a0Lo = smem_u32(smc + OFF_A0LO) + aOff;
    const uint32_t a1Hi = smem_u32(smc + OFF_A1HI) + aOff;
    const uint32_t a1Lo = smem_u32(smc + OFF_A1LO) + aOff;

    const uint4* W2fh4 = (const uint4*)g_W2fh;
    const uint4* W2fl4 = (const uint4*)g_W2fl;
    const uint4* B1fh4 = (const uint4*)(g_B1fh + (size_t)b * 8192);
    const uint4* B1fl4 = (const uint4*)(g_B1fl + (size_t)b * 8192);
    const int ng0 = wn * 2, ng1 = wn * 2 + 1;

    for (int tile = 0; tile < 4; tile++) {
        const int cur = tile & 1;
        const uint32_t aHi = cur ? a1Hi : a0Hi;
        const uint32_t aLo = cur ? a1Lo : a0Lo;
        uint32_t* nHi = (uint32_t*)(smc + (cur ? OFF_A0HI : OFF_A1HI));
        uint32_t* nLo = (uint32_t*)(smc + (cur ? OFF_A0LO : OFF_A1LO));
        const bool doStage = (tile < 3);
        const int nl0 = (tile + 1) * 64;

        float acc[2][4][4];
        #pragma unroll
        for (int mt = 0; mt < 2; mt++)
            #pragma unroll
            for (int nt = 0; nt < 4; nt++)
                #pragma unroll
                for (int r = 0; r < 4; r++) acc[mt][nt][r] = 0.0f;

        // ---- layer 1 GEMM (pipelined), staging of tile+1 interleaved ----
        {
            uint32_t ah[2][2][4], al[2][2][4];
            uint4 bh[2][2], bl[2][2];
            #define LOADG1(buf, kk) do { \
                ldsm_x4(ah[buf][0], aHi + (kk) * 32); \
                ldsm_x4(ah[buf][1], aHi + 16 * LDAB + (kk) * 32); \
                ldsm_x4(al[buf][0], aLo + (kk) * 32); \
                ldsm_x4(al[buf][1], aLo + 16 * LDAB + (kk) * 32); \
                bh[buf][0] = B1fh4[((kk) * 8 + ng0) * 32 + lane]; \
                bh[buf][1] = B1fh4[((kk) * 8 + ng1) * 32 + lane]; \
                bl[buf][0] = B1fl4[((kk) * 8 + ng0) * 32 + lane]; \
                bl[buf][1] = B1fl4[((kk) * 8 + ng1) * 32 + lane]; \
            } while (0)

            float4 skv, spv;            // staging pipeline regs
            bool sval = false;
            #define STAGE_LD(si) do { \
                int idx = (si) * 256 + t; \
                int l = idx >> 5, e4 = (idx & 31) * 4; \
                int gl = nl0 + l; \
                sval = (gl < LK); \
                if (sval) { \
                    skv = *(const float4*)(kb + (size_t)gl * EB + e4); \
                    spv = *(const float4*)(pos_emb + (size_t)gl * EB + e4); \
                } \
            } while (0)
            #define STAGE_ST(si) do { \
                int idx = (si) * 256 + t; \
                int l = idx >> 5, e4 = (idx & 31) * 4; \
                float x0 = 0, x1 = 0, x2 = 0, x3 = 0; \
                if (sval) { \
                    x0 = skv.x + spv.x; x1 = skv.y + spv.y; \
                    x2 = skv.z + spv.z; x3 = skv.w + spv.w; \
                } \
                uint32_t lo0, hi0 = packsplit(x0, x1, lo0); \
                uint32_t lo1, hi1 = packsplit(x2, x3, lo1); \
                *(uint2*)(nHi + l * 68 + (e4 >> 1)) = make_uint2(hi0, hi1); \
                *(uint2*)(nLo + l * 68 + (e4 >> 1)) = make_uint2(lo0, lo1); \
            } while (0)

            LOADG1(0, 0);
            if (doStage) STAGE_LD(0);
            #pragma unroll
            for (int k = 0; k < 8; k++) {
                const int cb = k & 1, nb = cb ^ 1;
                if (k < 7) LOADG1(nb, k + 1);
                if (doStage && k > 0) { STAGE_ST(k - 1); STAGE_LD(k); }
                #pragma unroll
                for (int mt = 0; mt < 2; mt++) {
                    mma_bf16(acc[mt][0], ah[cb][mt], bh[cb][0].x, bh[cb][0].y);
                    mma_bf16(acc[mt][1], ah[cb][mt], bh[cb][0].z, bh[cb][0].w);
                    mma_bf16(acc[mt][2], ah[cb][mt], bh[cb][1].x, bh[cb][1].y);
                    mma_bf16(acc[mt][3], ah[cb][mt], bh[cb][1].z, bh[cb][1].w);
                }
                #pragma unroll
                for (int mt = 0; mt < 2; mt++) {
                    mma_bf16(acc[mt][0], ah[cb][mt], bl[cb][0].x, bl[cb][0].y);
                    mma_bf16(acc[mt][1], ah[cb][mt], bl[cb][0].z, bl[cb][0].w);
                    mma_bf16(acc[mt][2], ah[cb][mt], bl[cb][1].x, bl[cb][1].y);
                    mma_bf16(acc[mt][3], ah[cb][mt], bl[cb][1].z, bl[cb][1].w);
                }
                #pragma unroll
                for (int mt = 0; mt < 2; mt++) {
                    mma_bf16(acc[mt][0], al[cb][mt], bh[cb][0].x, bh[cb][0].y);
                    mma_bf16(acc[mt][1], al[cb][mt], bh[cb][0].z, bh[cb][0].w);
                    mma_bf16(acc[mt][2], al[cb][mt], bh[cb][1].x, bh[cb][1].y);
                    mma_bf16(acc[mt][3], al[cb][mt], bh[cb][1].z, bh[cb][1].w);
                }
            }
            if (doStage) STAGE_ST(7);
            #undef LOADG1
            #undef STAGE_LD
            #undef STAGE_ST
        }
        __syncthreads();   // A reads + staging done

        // ---- epilogue 1: H1 = relu(z1 + u) -> current A buffer ----
        {
            uint32_t* hi = (uint32_t*)(smc + (cur ? OFF_A1HI : OFF_A0HI));
            uint32_t* lo = (uint32_t*)(smc + (cur ? OFF_A1LO : OFF_A0LO));
            const int rrow = lane >> 2;
            const int ccol = (lane & 3) * 2;
            #pragma unroll
            for (int mt = 0; mt < 2; mt++) {
                #pragma unroll
                for (int nt = 0; nt < 4; nt++) {
                    int c = n0 + nt * 8 + ccol;
                    float u0 = sU[c], u1 = sU[c + 1];
                    int r0 = m0 + mt * 16 + rrow;
                    float h0 = fmaxf(acc[mt][nt][0] + u0, 0.0f);
                    float h1 = fmaxf(acc[mt][nt][1] + u1, 0.0f);
                    uint32_t lop, hip = packsplit(h0, h1, lop);
                    uint32_t wi = r0 * 68 + (c >> 1);
                    hi[wi] = hip; lo[wi] = lop;
                    h0 = fmaxf(acc[mt][nt][2] + u0, 0.0f);
                    h1 = fmaxf(acc[mt][nt][3] + u1, 0.0f);
                    hip = packsplit(h0, h1, lop);
                    wi = (r0 + 8) * 68 + (c >> 1);
                    hi[wi] = hip; lo[wi] = lop;
                }
            }
        }
        __syncthreads();

        // ---- layer 2 GEMM (pipelined W2 from gmem) ----
        #pragma unroll
        for (int mt = 0; mt < 2; mt++)
            #pragma unroll
            for (int nt = 0; nt < 4; nt++)
                #pragma unroll
                for (int r = 0; r < 4; r++) acc[mt][nt][r] = 0.0f;

        {
            uint32_t ah[2][2][4], al[2][2][4];
            uint4 bh[2][2], bl[2][2];
            #define LOADG2(buf, kk) do { \
                ldsm_x4(ah[buf][0], aHi + (kk) * 32); \
                ldsm_x4(ah[buf][1], aHi + 16 * LDAB + (kk) * 32); \
                ldsm_x4(al[buf][0], aLo + (kk) * 32); \
                ldsm_x4(al[buf][1], aLo + 16 * LDAB + (kk) * 32); \
                bh[buf][0] = W2fh4[((kk) * 8 + ng0) * 32 + lane]; \
                bh[buf][1] = W2fh4[((kk) * 8 + ng1) * 32 + lane]; \
                bl[buf][0] = W2fl4[((kk) * 8 + ng0) * 32 + lane]; \
                bl[buf][1] = W2fl4[((kk) * 8 + ng1) * 32 + lane]; \
            } while (0)
            LOADG2(0, 0);
            #pragma unroll
            for (int k = 0; k < 8; k++) {
                const int cb = k & 1, nb = cb ^ 1;
                if (k < 7) LOADG2(nb, k + 1);
                #pragma unroll
                for (int mt = 0; mt < 2; mt++) {
                    mma_bf16(acc[mt][0], ah[cb][mt], bh[cb][0].x, bh[cb][0].y);
                    mma_bf16(acc[mt][1], ah[cb][mt], bh[cb][0].z, bh[cb][0].w);
                    mma_bf16(acc[mt][2], ah[cb][mt], bh[cb][1].x, bh[cb][1].y);
                    mma_bf16(acc[mt][3], ah[cb][mt], bh[cb][1].z, bh[cb][1].w);
                }
                #pragma unroll
                for (int mt = 0; mt < 2; mt++) {
                    mma_bf16(acc[mt][0], ah[cb][mt], bl[cb][0].x, bl[cb][0].y);
                    mma_bf16(acc[mt][1], ah[cb][mt], bl[cb][0].z, bl[cb][0].w);
                    mma_bf16(acc[mt][2], ah[cb][mt], bl[cb][1].x, bl[cb][1].y);
                    mma_bf16(acc[mt][3], ah[cb][mt], bl[cb][1].z, bl[cb][1].w);
                }
                #pragma unroll
                for (int mt = 0; mt < 2; mt++) {
                    mma_bf16(acc[mt][0], al[cb][mt], bh[cb][0].x, bh[cb][0].y);
                    mma_bf16(acc[mt][1], al[cb][mt], bh[cb][0].z, bh[cb][0].w);
                    mma_bf16(acc[mt][2], al[cb][mt], bh[cb][1].x, bh[cb][1].y);
                    mma_bf16(acc[mt][3], al[cb][mt], bh[cb][1].z, bh[cb][1].w);
                }
            }
            #undef LOADG2
        }

        // ---- epilogue 2: per-row partial scores ----
        {
            const int ccol = (lane & 3) * 2;
            #pragma unroll
            for (int mt = 0; mt < 2; mt++) {
                float p0 = 0.0f, p1 = 0.0f;
                #pragma unroll
                for (int nt = 0; nt < 4; nt++) {
                    int c = n0 + nt * 8 + ccol;
                    float bb0 = sBB[c], bb1 = sBB[c + 1];
                    float w30 = sW3[c], w31 = sW3[c + 1];
                    p0 += fmaxf(acc[mt][nt][0] + bb0, 0.0f) * w30
                        + fmaxf(acc[mt][nt][1] + bb1, 0.0f) * w31;
                    p1 += fmaxf(acc[mt][nt][2] + bb0, 0.0f) * w30
                        + fmaxf(acc[mt][nt][3] + bb1, 0.0f) * w31;
                }
                p0 += __shfl_xor_sync(0xffffffffu, p0, 1);
                p0 += __shfl_xor_sync(0xffffffffu, p0, 2);
                p1 += __shfl_xor_sync(0xffffffffu, p1, 1);
                p1 += __shfl_xor_sync(0xffffffffu, p1, 2);
                if ((lane & 3) == 0) {
                    int r = m0 + mt * 16 + (lane >> 2);
                    sRed[r * 4 + wn]       = p0;
                    sRed[(r + 8) * 4 + wn] = p1;
                }
            }
        }
        __syncthreads();

        if (t < 64) {
            float s4 = sRed[t * 4] + sRed[t * 4 + 1] + sRed[t * 4 + 2] + sRed[t * 4 + 3];
            sSc[tile * 64 + t] = s4 + b3v;
        }
    }
    __syncthreads();

    // ---- softmax over valid l ----
    int kli;
    if (g_len64) kli = (int)((const long long*)keys_length)[b];
    else         kli = ((const int*)keys_length)[b];
    kli = min(max(kli, 0), LK);

    float s = (t < kli) ? sSc[t] : -3.0e38f;
    float mw = s;
    #pragma unroll
    for (int off = 16; off > 0; off >>= 1)
        mw = fmaxf(mw, __shfl_down_sync(0xffffffffu, mw, off));
    if (lane == 0) sRed[w] = mw;
    __syncthreads();
    float m = sRed[0];
    #pragma unroll
    for (int ww = 1; ww < 8; ww++) m = fmaxf(m, sRed[ww]);

    float wgt = (t < kli) ? expf(s - m) : 0.0f;
    sSc[t] = wgt;
    float sw = wgt;
    #pragma unroll
    for (int off = 16; off > 0; off >>= 1)
        sw += __shfl_down_sync(0xffffffffu, sw, off);
    if (lane == 0) sRed[8 + w] = sw;
    __syncthreads();
    float tot = 0.0f;
    #pragma unroll
    for (int ww = 0; ww < 8; ww++) tot += sRed[8 + ww];
    const float inv = 1.0f / tot;
    __syncthreads();

    // ---- weighted sum of keys_p ----
    {
        int ei = t & 127, half = t >> 7;
        float acc2 = 0.0f;
        #pragma unroll 4
        for (int l = half; l < kli; l += 2)
            acc2 += sSc[l] * (kb[(size_t)l * EB + ei] + pos_emb[(size_t)l * EB + ei]);
        sRed[t] = acc2;
        __syncthreads();
        if (t < 128)
            out[(size_t)b * EB + t] = (sRed[t] + sRed[t + 128]) * inv;
    }
}

extern "C" void kernel_launch(void* const* d_in, const int* in_sizes, int n_in,
                              void* d_out, int out_size) {
    const float* query       = (const float*)d_in[0];
    const float* keys        = (const float*)d_in[1];
    const void*  keys_length = d_in[2];
    const float* pos_emb     = (const float*)d_in[3];
    const float* W1          = (const float*)d_in[4];
    const float* b1          = (const float*)d_in[5];
    const float* W2          = (const float*)d_in[6];
    const float* b2          = (const float*)d_in[7];
    const float* W3          = (const float*)d_in[8];
    const float* b3          = (const float*)d_in[9];
    float* out = (float*)d_out;

    const int B = in_sizes[2];  // 4096

    static int attr_done = 0;
    if (!attr_done) {
        cudaFuncSetAttribute(din_kernel, cudaFuncAttributeMaxDynamicSharedMemorySize, SMEM_BYTES);
        attr_done = 1;
    }

    prep_kernel<<<97, 256>>>(W1, W2, (const unsigned int*)keys_length, B);
    bstage_kernel<<<NB, 256>>>(query, b1);
    din_kernel<<<NB, 256, SMEM_BYTES>>>(keys, keys_length, pos_emb,
                                        b2, W3, b3, out);
}

// round 15
// speedup vs baseline: 1.6658x; 1.5113x over previous
#include <cuda_runtime.h>
#include <cuda_bf16.h>
#include <cstdint>

// DIN sequence encoder, B=4096, L=200, E=A=128.
// Factorization: att_in@W1 = q@(W1a+W1c) + keys_p@[(W1b-W1c) + diag(q)*W1d]
// 256 threads/CTA, 2 CTAs/SM. mma.sync bf16 3-term split, 32x32 warp tiles.
// B1 (q-dependent) pre-built as mma fragment images in gmem (bstage kernel,
// which also computes the per-batch bias u). A-tile staging for tile t+1 is
// hidden inside tile t's GEMM1 k-loop. Tiles fully beyond keys_length[b]
// are skipped entirely (their scores are softmax-masked and never read).

#define EB 128
#define AB 128
#define LK 200
#define NB 4096
#define LDAE 136
#define LDAB (LDAE * 2)          // 272 B row stride

__device__ float g_W1kT[EB * AB];                    // [n][e] = (W1b - W1c)^T
__device__ float g_W1dT[EB * AB];                    // [n][e] = W1d^T
__device__ float g_W1q[EB * AB];                     // [e][n] = W1a + W1c
__device__ __align__(16) uint32_t g_W2fh[8192];      // W2 fragment images (hi)
__device__ __align__(16) uint32_t g_W2fl[8192];      // W2 fragment images (lo)
__device__ __align__(16) uint32_t g_B1fh[(size_t)NB * 8192];  // per-batch B1 frags hi
__device__ __align__(16) uint32_t g_B1fl[(size_t)NB * 8192];  // per-batch B1 frags lo
__device__ float g_U[NB * AB];                       // u = q @ (W1a+W1c) + b1
__device__ int   g_len64;

// fast fp32 -> bf16 hi/lo split, packed pairs (x0 in low half)
__device__ __forceinline__ uint32_t packsplit(float x0, float x1, uint32_t& lop) {
    uint32_t hip;
    asm("cvt.rn.bf16x2.f32 %0, %1, %2;" : "=r"(hip) : "f"(x1), "f"(x0));
    float h0 = __uint_as_float(hip << 16);
    float h1 = __uint_as_float(hip & 0xFFFF0000u);
    float r0 = x0 - h0, r1 = x1 - h1;
    asm("cvt.rn.bf16x2.f32 %0, %1, %2;" : "=r"(lop) : "f"(r1), "f"(r0));
    return hip;
}

// ---------------- prep kernel: grid 97 x 256 (all-parallel, ~5us) ----------------
__global__ void prep_kernel(const float* __restrict__ W1,
                            const float* __restrict__ W2,
                            const unsigned int* __restrict__ kl_words, int B) {
    const int t = threadIdx.x;
    const int blk = blockIdx.x;

    if (blk < 64) {                       // W1 transposes + W1q sum (fp32)
        int i = blk * 256 + t;
        int e = i >> 7, n = i & 127;
        float wa = W1[e * AB + n];
        float wb = W1[EB * AB + e * AB + n];
        float wc = W1[2 * EB * AB + e * AB + n];
        float wd = W1[3 * EB * AB + e * AB + n];
        g_W1kT[n * EB + e] = wb - wc;
        g_W1dT[n * EB + e] = wd;
        g_W1q[i] = wa + wc;               // [e][n]
        return;
    }
    if (blk < 96) {                       // W2 fragment images for mma B operand
        int i = (blk - 64) * 256 + t;     // 0..8191
        int j = i & 3, lane = (i >> 2) & 31, ng = (i >> 7) & 7, s = i >> 10;
        int n  = ng * 16 + ((j >> 1) << 3) + (lane >> 2);
        int k0 = s * 16 + (lane & 3) * 2 + ((j & 1) ? 8 : 0);
        float a = W2[k0 * AB + n];
        float bv = W2[(k0 + 1) * AB + n];
        uint32_t lop, hip = packsplit(a, bv, lop);
        g_W2fh[i] = hip;
        g_W2fl[i] = lop;
        return;
    }
    // blk == 96: keys_length dtype sniffer
    int local = 0;
    for (int i = t; i < B / 2; i += 256)
        if (kl_words[2 * i + 1] != 0u) local = 1;
    int any = __syncthreads_or(local);
    if (t == 0) g_len64 = any ? 0 : 1;
}

// ---------------- bstage kernel: per-batch B1 fragment images + u ----------------
__global__ void bstage_kernel(const float* __restrict__ query,
                              const float* __restrict__ b1) {
    __shared__ float sq[128];
    __shared__ float su[2][128];
    const int b = blockIdx.x, t = threadIdx.x;
    if (t < 128) sq[t] = query[(size_t)b * EB + t];
    __syncthreads();

    // ---- u = q @ (W1a+W1c) + b1, split across 2 thread halves ----
    {
        int n = t & 127, half = t >> 7;
        float acc = 0.0f;
        #pragma unroll 8
        for (int e = half * 64; e < half * 64 + 64; e++)
            acc += sq[e] * g_W1q[e * AB + n];
        su[half][n] = acc;
    }

    // ---- B1 fragment images ----
    uint32_t* outh = g_B1fh + (size_t)b * 8192;
    uint32_t* outl = g_B1fl + (size_t)b * 8192;
    #pragma unroll 4
    for (int ii = 0; ii < 32; ii++) {
        int i = ii * 256 + t;
        int j = i & 3, lane = (i >> 2) & 31, ng = (i >> 7) & 7, s = i >> 10;
        int n  = ng * 16 + ((j >> 1) << 3) + (lane >> 2);
        int k0 = s * 16 + (lane & 3) * 2 + ((j & 1) ? 8 : 0);
        float x0 = g_W1kT[n * EB + k0]     + sq[k0]     * g_W1dT[n * EB + k0];
        float x1 = g_W1kT[n * EB + k0 + 1] + sq[k0 + 1] * g_W1dT[n * EB + k0 + 1];
        uint32_t lop, hip = packsplit(x0, x1, lop);
        outh[i] = hip;
        outl[i] = lop;
    }

    __syncthreads();
    if (t < 128) g_U[(size_t)b * AB + t] = su[0][t] + su[1][t] + b1[t];
}

// ---------------- MMA helpers ----------------
__device__ __forceinline__ uint32_t smem_u32(const void* p) {
    uint32_t a;
    asm("{ .reg .u64 tmp; cvta.to.shared.u64 tmp, %1; cvt.u32.u64 %0, tmp; }"
        : "=r"(a) : "l"(p));
    return a;
}
__device__ __forceinline__ void ldsm_x4(uint32_t* r, uint32_t addr) {
    asm volatile("ldmatrix.sync.aligned.m8n8.x4.shared.b16 {%0,%1,%2,%3}, [%4];"
                 : "=r"(r[0]), "=r"(r[1]), "=r"(r[2]), "=r"(r[3]) : "r"(addr));
}
__device__ __forceinline__ void mma_bf16(float* d, const uint32_t* a,
                                         uint32_t b0, uint32_t b1) {
    asm volatile("mma.sync.aligned.m16n8k16.row.col.f32.bf16.bf16.f32 "
                 "{%0,%1,%2,%3},{%4,%5,%6,%7},{%8,%9},{%0,%1,%2,%3};"
                 : "+f"(d[0]), "+f"(d[1]), "+f"(d[2]), "+f"(d[3])
                 : "r"(a[0]), "r"(a[1]), "r"(a[2]), "r"(a[3]), "r"(b0), "r"(b1));
}

// ---------------- SMEM layout (bytes) ----------------
#define OFF_A0HI 0                        // 64*272 = 17408
#define OFF_A0LO 17408
#define OFF_A1HI 34816
#define OFF_A1LO 52224
#define OFF_U    69632                    // 128 f
#define OFF_BB2  70144
#define OFF_W3   70656
#define OFF_SC   71168                    // 256 f
#define OFF_RED  72192                    // 512 f
#define SMEM_BYTES 74240

__global__ void __launch_bounds__(256, 2) din_kernel(
    const float* __restrict__ keys,
    const void*  __restrict__ keys_length,
    const float* __restrict__ pos_emb,
    const float* __restrict__ b2,
    const float* __restrict__ W3,
    const float* __restrict__ b3,
    float* __restrict__ out)
{
    extern __shared__ char smc[];
    float* sU   = (float*)(smc + OFF_U);
    float* sBB  = (float*)(smc + OFF_BB2);
    float* sW3  = (float*)(smc + OFF_W3);
    float* sSc  = (float*)(smc + OFF_SC);
    float* sRed = (float*)(smc + OFF_RED);

    const int b = blockIdx.x;
    const int t = threadIdx.x;
    const int w = t >> 5, lane = t & 31;

    // ---- valid length: rows >= kli are softmax-masked -> skip whole tiles ----
    int kli;
    if (g_len64) kli = (int)((const long long*)keys_length)[b];
    else         kli = ((const int*)keys_length)[b];
    kli = min(max(kli, 1), LK);
    const int ntiles = (kli + 63) >> 6;        // 1..4

    if (t < 128) {
        sU[t]  = g_U[(size_t)b * AB + t];
        sBB[t] = b2[t];
        sW3[t] = W3[t];
    }
    const float b3v = b3[0];
    const float* kb = keys + (size_t)b * LK * EB;

    // ---- stage tile 0 into buffer 0 ----
    {
        uint32_t* hi = (uint32_t*)(smc + OFF_A0HI);
        uint32_t* lo = (uint32_t*)(smc + OFF_A0LO);
        #pragma unroll
        for (int si = 0; si < 8; si++) {
            int idx = si * 256 + t;
            int l = idx >> 5, e4 = (idx & 31) * 4;
            float x0 = 0, x1 = 0, x2 = 0, x3 = 0;
            {
                float4 kv = *(const float4*)(kb + (size_t)l * EB + e4);
                float4 pv = *(const float4*)(pos_emb + (size_t)l * EB + e4);
                x0 = kv.x + pv.x; x1 = kv.y + pv.y; x2 = kv.z + pv.z; x3 = kv.w + pv.w;
            }
            uint32_t lo0, hi0 = packsplit(x0, x1, lo0);
            uint32_t lo1, hi1 = packsplit(x2, x3, lo1);
            *(uint2*)(hi + l * 68 + (e4 >> 1)) = make_uint2(hi0, hi1);
            *(uint2*)(lo + l * 68 + (e4 >> 1)) = make_uint2(lo0, lo1);
        }
    }
    __syncthreads();

    // 32x32 warp tiles: 2 m-groups x 4 n-groups
    const int wm = w >> 2, wn = w & 3;
    const int m0 = wm * 32, n0 = wn * 32;
    const uint32_t lrow  = (((lane >> 3) & 1) << 3) + (lane & 7);
    const uint32_t lcolb = (lane >> 4) << 4;
    const uint32_t aOff  = (m0 + lrow) * LDAB + lcolb;

    const uint32_t a0Hi = smem_u32(smc + OFF_A0HI) + aOff;
    const uint32_t a0Lo = smem_u32(smc + OFF_A0LO) + aOff;
    const uint32_t a1Hi = smem_u32(smc + OFF_A1HI) + aOff;
    const uint32_t a1Lo = smem_u32(smc + OFF_A1LO) + aOff;

    const uint4* W2fh4 = (const uint4*)g_W2fh;
    const uint4* W2fl4 = (const uint4*)g_W2fl;
    const uint4* B1fh4 = (const uint4*)(g_B1fh + (size_t)b * 8192);
    const uint4* B1fl4 = (const uint4*)(g_B1fl + (size_t)b * 8192);
    const int ng0 = wn * 2, ng1 = wn * 2 + 1;

    for (int tile = 0; tile < ntiles; tile++) {
        const int cur = tile & 1;
        const uint32_t aHi = cur ? a1Hi : a0Hi;
        const uint32_t aLo = cur ? a1Lo : a0Lo;
        uint32_t* nHi = (uint32_t*)(smc + (cur ? OFF_A0HI : OFF_A1HI));
        uint32_t* nLo = (uint32_t*)(smc + (cur ? OFF_A0LO : OFF_A1LO));
        const bool doStage = (tile + 1 < ntiles);
        const int nl0 = (tile + 1) * 64;

        float acc[2][4][4];
        #pragma unroll
        for (int mt = 0; mt < 2; mt++)
            #pragma unroll
            for (int nt = 0; nt < 4; nt++)
                #pragma unroll
                for (int r = 0; r < 4; r++) acc[mt][nt][r] = 0.0f;

        // ---- layer 1 GEMM (pipelined), staging of tile+1 interleaved ----
        {
            uint32_t ah[2][2][4], al[2][2][4];
            uint4 bh[2][2], bl[2][2];
            #define LOADG1(buf, kk) do { \
                ldsm_x4(ah[buf][0], aHi + (kk) * 32); \
                ldsm_x4(ah[buf][1], aHi + 16 * LDAB + (kk) * 32); \
                ldsm_x4(al[buf][0], aLo + (kk) * 32); \
                ldsm_x4(al[buf][1], aLo + 16 * LDAB + (kk) * 32); \
                bh[buf][0] = B1fh4[((kk) * 8 + ng0) * 32 + lane]; \
                bh[buf][1] = B1fh4[((kk) * 8 + ng1) * 32 + lane]; \
                bl[buf][0] = B1fl4[((kk) * 8 + ng0) * 32 + lane]; \
                bl[buf][1] = B1fl4[((kk) * 8 + ng1) * 32 + lane]; \
            } while (0)

            float4 skv, spv;            // staging pipeline regs
            bool sval = false;
            #define STAGE_LD(si) do { \
                int idx = (si) * 256 + t; \
                int l = idx >> 5, e4 = (idx & 31) * 4; \
                int gl = nl0 + l; \
                sval = (gl < LK); \
                if (sval) { \
                    skv = *(const float4*)(kb + (size_t)gl * EB + e4); \
                    spv = *(const float4*)(pos_emb + (size_t)gl * EB + e4); \
                } \
            } while (0)
            #define STAGE_ST(si) do { \
                int idx = (si) * 256 + t; \
                int l = idx >> 5, e4 = (idx & 31) * 4; \
                float x0 = 0, x1 = 0, x2 = 0, x3 = 0; \
                if (sval) { \
                    x0 = skv.x + spv.x; x1 = skv.y + spv.y; \
                    x2 = skv.z + spv.z; x3 = skv.w + spv.w; \
                } \
                uint32_t lo0, hi0 = packsplit(x0, x1, lo0); \
                uint32_t lo1, hi1 = packsplit(x2, x3, lo1); \
                *(uint2*)(nHi + l * 68 + (e4 >> 1)) = make_uint2(hi0, hi1); \
                *(uint2*)(nLo + l * 68 + (e4 >> 1)) = make_uint2(lo0, lo1); \
            } while (0)

            LOADG1(0, 0);
            if (doStage) STAGE_LD(0);
            #pragma unroll
            for (int k = 0; k < 8; k++) {
                const int cb = k & 1, nb = cb ^ 1;
                if (k < 7) LOADG1(nb, k + 1);
                if (doStage && k > 0) { STAGE_ST(k - 1); STAGE_LD(k); }
                #pragma unroll
                for (int mt = 0; mt < 2; mt++) {
                    mma_bf16(acc[mt][0], ah[cb][mt], bh[cb][0].x, bh[cb][0].y);
                    mma_bf16(acc[mt][1], ah[cb][mt], bh[cb][0].z, bh[cb][0].w);
                    mma_bf16(acc[mt][2], ah[cb][mt], bh[cb][1].x, bh[cb][1].y);
                    mma_bf16(acc[mt][3], ah[cb][mt], bh[cb][1].z, bh[cb][1].w);
                }
                #pragma unroll
                for (int mt = 0; mt < 2; mt++) {
                    mma_bf16(acc[mt][0], ah[cb][mt], bl[cb][0].x, bl[cb][0].y);
                    mma_bf16(acc[mt][1], ah[cb][mt], bl[cb][0].z, bl[cb][0].w);
                    mma_bf16(acc[mt][2], ah[cb][mt], bl[cb][1].x, bl[cb][1].y);
                    mma_bf16(acc[mt][3], ah[cb][mt], bl[cb][1].z, bl[cb][1].w);
                }
                #pragma unroll
                for (int mt = 0; mt < 2; mt++) {
                    mma_bf16(acc[mt][0], al[cb][mt], bh[cb][0].x, bh[cb][0].y);
                    mma_bf16(acc[mt][1], al[cb][mt], bh[cb][0].z, bh[cb][0].w);
                    mma_bf16(acc[mt][2], al[cb][mt], bh[cb][1].x, bh[cb][1].y);
                    mma_bf16(acc[mt][3], al[cb][mt], bh[cb][1].z, bh[cb][1].w);
                }
            }
            if (doStage) STAGE_ST(7);
            #undef LOADG1
            #undef STAGE_LD
            #undef STAGE_ST
        }
        __syncthreads();   // A reads + staging done

        // ---- epilogue 1: H1 = relu(z1 + u) -> current A buffer ----
        {
            uint32_t* hi = (uint32_t*)(smc + (cur ? OFF_A1HI : OFF_A0HI));
            uint32_t* lo = (uint32_t*)(smc + (cur ? OFF_A1LO : OFF_A0LO));
            const int rrow = lane >> 2;
            const int ccol = (lane & 3) * 2;
            #pragma unroll
            for (int mt = 0; mt < 2; mt++) {
                #pragma unroll
                for (int nt = 0; nt < 4; nt++) {
                    int c = n0 + nt * 8 + ccol;
                    float u0 = sU[c], u1 = sU[c + 1];
                    int r0 = m0 + mt * 16 + rrow;
                    float h0 = fmaxf(acc[mt][nt][0] + u0, 0.0f);
                    float h1 = fmaxf(acc[mt][nt][1] + u1, 0.0f);
                    uint32_t lop, hip = packsplit(h0, h1, lop);
                    uint32_t wi = r0 * 68 + (c >> 1);
                    hi[wi] = hip; lo[wi] = lop;
                    h0 = fmaxf(acc[mt][nt][2] + u0, 0.0f);
                    h1 = fmaxf(acc[mt][nt][3] + u1, 0.0f);
                    hip = packsplit(h0, h1, lop);
                    wi = (r0 + 8) * 68 + (c >> 1);
                    hi[wi] = hip; lo[wi] = lop;
                }
            }
        }
        __syncthreads();

        // ---- layer 2 GEMM (pipelined W2 from gmem) ----
        #pragma unroll
        for (int mt = 0; mt < 2; mt++)
            #pragma unroll
            for (int nt = 0; nt < 4; nt++)
                #pragma unroll
                for (int r = 0; r < 4; r++) acc[mt][nt][r] = 0.0f;

        {
            uint32_t ah[2][2][4], al[2][2][4];
            uint4 bh[2][2], bl[2][2];
            #define LOADG2(buf, kk) do { \
                ldsm_x4(ah[buf][0], aHi + (kk) * 32); \
                ldsm_x4(ah[buf][1], aHi + 16 * LDAB + (kk) * 32); \
                ldsm_x4(al[buf][0], aLo + (kk) * 32); \
                ldsm_x4(al[buf][1], aLo + 16 * LDAB + (kk) * 32); \
                bh[buf][0] = W2fh4[((kk) * 8 + ng0) * 32 + lane]; \
                bh[buf][1] = W2fh4[((kk) * 8 + ng1) * 32 + lane]; \
                bl[buf][0] = W2fl4[((kk) * 8 + ng0) * 32 + lane]; \
                bl[buf][1] = W2fl4[((kk) * 8 + ng1) * 32 + lane]; \
            } while (0)
            LOADG2(0, 0);
            #pragma unroll
            for (int k = 0; k < 8; k++) {
                const int cb = k & 1, nb = cb ^ 1;
                if (k < 7) LOADG2(nb, k + 1);
                #pragma unroll
                for (int mt = 0; mt < 2; mt++) {
                    mma_bf16(acc[mt][0], ah[cb][mt], bh[cb][0].x, bh[cb][0].y);
                    mma_bf16(acc[mt][1], ah[cb][mt], bh[cb][0].z, bh[cb][0].w);
                    mma_bf16(acc[mt][2], ah[cb][mt], bh[cb][1].x, bh[cb][1].y);
                    mma_bf16(acc[mt][3], ah[cb][mt], bh[cb][1].z, bh[cb][1].w);
                }
                #pragma unroll
                for (int mt = 0; mt < 2; mt++) {
                    mma_bf16(acc[mt][0], ah[cb][mt], bl[cb][0].x, bl[cb][0].y);
                    mma_bf16(acc[mt][1], ah[cb][mt], bl[cb][0].z, bl[cb][0].w);
                    mma_bf16(acc[mt][2], ah[cb][mt], bl[cb][1].x, bl[cb][1].y);
                    mma_bf16(acc[mt][3], ah[cb][mt], bl[cb][1].z, bl[cb][1].w);
                }
                #pragma unroll
                for (int mt = 0; mt < 2; mt++) {
                    mma_bf16(acc[mt][0], al[cb][mt], bh[cb][0].x, bh[cb][0].y);
                    mma_bf16(acc[mt][1], al[cb][mt], bh[cb][0].z, bh[cb][0].w);
                    mma_bf16(acc[mt][2], al[cb][mt], bh[cb][1].x, bh[cb][1].y);
                    mma_bf16(acc[mt][3], al[cb][mt], bh[cb][1].z, bh[cb][1].w);
                }
            }
            #undef LOADG2
        }

        // ---- epilogue 2: per-row partial scores ----
        {
            const int ccol = (lane & 3) * 2;
            #pragma unroll
            for (int mt = 0; mt < 2; mt++) {
                float p0 = 0.0f, p1 = 0.0f;
                #pragma unroll
                for (int nt = 0; nt < 4; nt++) {
                    int c = n0 + nt * 8 + ccol;
                    float bb0 = sBB[c], bb1 = sBB[c + 1];
                    float w30 = sW3[c], w31 = sW3[c + 1];
                    p0 += fmaxf(acc[mt][nt][0] + bb0, 0.0f) * w30
                        + fmaxf(acc[mt][nt][1] + bb1, 0.0f) * w31;
                    p1 += fmaxf(acc[mt][nt][2] + bb0, 0.0f) * w30
                        + fmaxf(acc[mt][nt][3] + bb1, 0.0f) * w31;
                }
                p0 += __shfl_xor_sync(0xffffffffu, p0, 1);
                p0 += __shfl_xor_sync(0xffffffffu, p0, 2);
                p1 += __shfl_xor_sync(0xffffffffu, p1, 1);
                p1 += __shfl_xor_sync(0xffffffffu, p1, 2);
                if ((lane & 3) == 0) {
                    int r = m0 + mt * 16 + (lane >> 2);
                    sRed[r * 4 + wn]       = p0;
                    sRed[(r + 8) * 4 + wn] = p1;
                }
            }
        }
        __syncthreads();

        if (t < 64) {
            float s4 = sRed[t * 4] + sRed[t * 4 + 1] + sRed[t * 4 + 2] + sRed[t * 4 + 3];
            sSc[tile * 64 + t] = s4 + b3v;
        }
    }
    __syncthreads();

    // ---- softmax over valid l ----
    float s = (t < kli) ? sSc[t] : -3.0e38f;
    float mw = s;
    #pragma unroll
    for (int off = 16; off > 0; off >>= 1)
        mw = fmaxf(mw, __shfl_down_sync(0xffffffffu, mw, off));
    if (lane == 0) sRed[w] = mw;
    __syncthreads();
    float m = sRed[0];
    #pragma unroll
    for (int ww = 1; ww < 8; ww++) m = fmaxf(m, sRed[ww]);

    float wgt = (t < kli) ? expf(s - m) : 0.0f;
    sSc[t] = wgt;
    float sw = wgt;
    #pragma unroll
    for (int off = 16; off > 0; off >>= 1)
        sw += __shfl_down_sync(0xffffffffu, sw, off);
    if (lane == 0) sRed[8 + w] = sw;
    __syncthreads();
    float tot = 0.0f;
    #pragma unroll
    for (int ww = 0; ww < 8; ww++) tot += sRed[8 + ww];
    const float inv = 1.0f / tot;
    __syncthreads();

    // ---- weighted sum of keys_p ----
    {
        int ei = t & 127, half = t >> 7;
        float acc2 = 0.0f;
        #pragma unroll 4
        for (int l = half; l < kli; l += 2)
            acc2 += sSc[l] * (kb[(size_t)l * EB + ei] + pos_emb[(size_t)l * EB + ei]);
        sRed[t] = acc2;
        __syncthreads();
        if (t < 128)
            out[(size_t)b * EB + t] = (sRed[t] + sRed[t + 128]) * inv;
    }
}

extern "C" void kernel_launch(void* const* d_in, const int* in_sizes, int n_in,
                              void* d_out, int out_size) {
    const float* query       = (const float*)d_in[0];
    const float* keys        = (const float*)d_in[1];
    const void*  keys_length = d_in[2];
    const float* pos_emb     = (const float*)d_in[3];
    const float* W1          = (const float*)d_in[4];
    const float* b1          = (const float*)d_in[5];
    const float* W2          = (const float*)d_in[6];
    const float* b2          = (const float*)d_in[7];
    const float* W3          = (const float*)d_in[8];
    const float* b3          = (const float*)d_in[9];
    float* out = (float*)d_out;

    const int B = in_sizes[2];  // 4096

    static int attr_done = 0;
    if (!attr_done) {
        cudaFuncSetAttribute(din_kernel, cudaFuncAttributeMaxDynamicSharedMemorySize, SMEM_BYTES);
        attr_done = 1;
    }

    prep_kernel<<<97, 256>>>(W1, W2, (const unsigned int*)keys_length, B);
    bstage_kernel<<<NB, 256>>>(query, b1);
    din_kernel<<<NB, 256, SMEM_BYTES>>>(keys, keys_length, pos_emb,
                                        b2, W3, b3, out);
}